// round 16
// baseline (speedup 1.0000x reference)
#include <cuda_runtime.h>
#include <cuda_bf16.h>
#include <cuda_fp16.h>
#include <cstdint>

#define DIMC   1024
#define BATCH  4
#define SEQL   2048
#define NHEADS 16
#define HDIM   64
#define NROWS  (BATCH*SEQL)   // 8192

typedef unsigned long long ull;

// ---- scratch: __device__ globals (no cudaMalloc anywhere) -------------------
__device__ __align__(16) __nv_bfloat16 g_xh[NROWS*DIMC], g_xl[NROWS*DIMC];
__device__ __align__(16) __nv_bfloat16 g_ch[NROWS*DIMC], g_cl[NROWS*DIMC];
__device__ __align__(16) __nv_bfloat16 g_wqh[DIMC*DIMC], g_wql[DIMC*DIMC];
__device__ __align__(16) __nv_bfloat16 g_wkh[DIMC*DIMC], g_wkl[DIMC*DIMC];
__device__ __align__(16) __nv_bfloat16 g_wvh[DIMC*DIMC], g_wvl[DIMC*DIMC];
__device__ __align__(16) __nv_bfloat16 g_woh[DIMC*DIMC], g_wol[DIMC*DIMC];
__device__ __align__(16) __half        g_qh[NROWS*DIMC];
__device__ __align__(16) __half        g_kh[NROWS*DIMC];
__device__ __align__(16) __half        g_vh[NROWS*DIMC];
__device__ __align__(16) __nv_bfloat16 g_aoh[NROWS*DIMC], g_aol[NROWS*DIMC];

// ---- common helpers ---------------------------------------------------------
__device__ __forceinline__ void split4(float4 v, ull& hi, ull& lo) {
    union { __nv_bfloat16 b[4]; ull u; } H, L;
    float x[4] = {v.x, v.y, v.z, v.w};
    #pragma unroll
    for (int i = 0; i < 4; i++) {
        __nv_bfloat16 h = __float2bfloat16(x[i]);
        H.b[i] = h;
        L.b[i] = __float2bfloat16(x[i] - __bfloat162float(h));
    }
    hi = H.u; lo = L.u;
}

__device__ __forceinline__ void cpa16(void* dst, const void* src) {
    uint32_t d = (uint32_t)__cvta_generic_to_shared(dst);
    asm volatile("cp.async.cg.shared.global [%0], [%1], 16;" :: "r"(d), "l"(src));
}
#define CP_COMMIT() asm volatile("cp.async.commit_group;")
template <int N>
__device__ __forceinline__ void cp_wait() {
    asm volatile("cp.async.wait_group %0;" :: "n"(N));
}

__device__ __forceinline__ void ldmx4(uint32_t* r, const void* p) {
    uint32_t a = (uint32_t)__cvta_generic_to_shared(p);
    asm volatile("ldmatrix.sync.aligned.m8n8.x4.shared.b16 {%0,%1,%2,%3}, [%4];"
        : "=r"(r[0]), "=r"(r[1]), "=r"(r[2]), "=r"(r[3]) : "r"(a));
}
__device__ __forceinline__ void ldmx4t(uint32_t* r, const void* p) {
    uint32_t a = (uint32_t)__cvta_generic_to_shared(p);
    asm volatile("ldmatrix.sync.aligned.m8n8.x4.trans.shared.b16 {%0,%1,%2,%3}, [%4];"
        : "=r"(r[0]), "=r"(r[1]), "=r"(r[2]), "=r"(r[3]) : "r"(a));
}
__device__ __forceinline__ void mma16816(float* c, const uint32_t* a,
                                         uint32_t b0, uint32_t b1) {
    asm volatile(
        "mma.sync.aligned.m16n8k16.row.col.f32.bf16.bf16.f32 "
        "{%0,%1,%2,%3}, {%4,%5,%6,%7}, {%8,%9}, {%0,%1,%2,%3};"
        : "+f"(c[0]), "+f"(c[1]), "+f"(c[2]), "+f"(c[3])
        : "r"(a[0]), "r"(a[1]), "r"(a[2]), "r"(a[3]), "r"(b0), "r"(b1));
}
__device__ __forceinline__ void mmaf16(float* c, const uint32_t* a,
                                       uint32_t b0, uint32_t b1) {
    asm volatile(
        "mma.sync.aligned.m16n8k16.row.col.f32.f16.f16.f32 "
        "{%0,%1,%2,%3}, {%4,%5,%6,%7}, {%8,%9}, {%0,%1,%2,%3};"
        : "+f"(c[0]), "+f"(c[1]), "+f"(c[2]), "+f"(c[3])
        : "r"(a[0]), "r"(a[1]), "r"(a[2]), "r"(a[3]), "r"(b0), "r"(b1));
}
__device__ __forceinline__ uint32_t pack_h2(float lo, float hi) {
    uint32_t r;
    asm("cvt.rn.f16x2.f32 %0, %1, %2;" : "=r"(r) : "f"(hi), "f"(lo));
    return r;
}

// ============================================================================
// One-shot splits, MLP=4 (each thread loads 4 independent float4 first).
// ============================================================================
__global__ void split_act_k(const float* __restrict__ x,
                            const float* __restrict__ ctx)
{
    const float* src = blockIdx.y ? ctx : x;
    __nv_bfloat16* hi = blockIdx.y ? g_ch : g_xh;
    __nv_bfloat16* lo = blockIdx.y ? g_cl : g_xl;
    int i0 = (blockIdx.x * 256 + threadIdx.x) * 4;
    float4 v[4];
    #pragma unroll
    for (int j = 0; j < 4; j++) v[j] = ((const float4*)src)[i0 + j];
    #pragma unroll
    for (int j = 0; j < 4; j++) {
        ull h, l; split4(v[j], h, l);
        ((ull*)hi)[i0 + j] = h;
        ((ull*)lo)[i0 + j] = l;
    }
}

__global__ void split_w_k(const float* __restrict__ Wq,
                          const float* __restrict__ Wk,
                          const float* __restrict__ Wv,
                          const float* __restrict__ Wo)
{
    const float* src;
    __nv_bfloat16 *hi, *lo;
    switch (blockIdx.y) {
        case 0: src = Wq; hi = g_wqh; lo = g_wql; break;
        case 1: src = Wk; hi = g_wkh; lo = g_wkl; break;
        case 2: src = Wv; hi = g_wvh; lo = g_wvl; break;
        default: src = Wo; hi = g_woh; lo = g_wol; break;
    }
    int i0 = (blockIdx.x * 256 + threadIdx.x) * 4;
    float4 v[4];
    #pragma unroll
    for (int j = 0; j < 4; j++) v[j] = ((const float4*)src)[i0 + j];
    #pragma unroll
    for (int j = 0; j < 4; j++) {
        ull h, l; split4(v[j], h, l);
        ((ull*)hi)[i0 + j] = h;
        ((ull*)lo)[i0 + j] = l;
    }
}

// ============================================================================
// GEMM on pre-split bf16, 3-stage cp.async pipeline, ONE sync per slab.
// 128x128x32 tiles, 512 threads, warp tile 32x32, bf16x3 triple.
// ============================================================================
#define TBM 128
#define TBN 128
#define TBK 32
#define STG 32768          // bytes/stage (Ah|Al|Wh|Wl, 8KB each)
#define NSTG 3

__device__ __forceinline__ int toff(int row, int k) {
    return row * 64 + ((((k >> 3) ^ ((row >> 1) & 3)) & 3) << 4);
}

extern __shared__ char dynsmem[];

__global__ __launch_bounds__(512, 1)
void gemm_tc3(const float* __restrict__ bias, float* __restrict__ Cext,
              int asel, int wsel, int osel, float oscale)
{
    const __nv_bfloat16 *Ah, *Al, *Wh, *Wl;
    switch (asel) {
        case 0: Ah = g_xh;  Al = g_xl;  break;
        case 1: Ah = g_ch;  Al = g_cl;  break;
        default: Ah = g_aoh; Al = g_aol; break;
    }
    switch (wsel) {
        case 0: Wh = g_wqh; Wl = g_wql; break;
        case 1: Wh = g_wkh; Wl = g_wkl; break;
        case 2: Wh = g_wvh; Wl = g_wvl; break;
        default: Wh = g_woh; Wl = g_wol; break;
    }

    const int bm = blockIdx.y * TBM;
    const int bn = blockIdx.x * TBN;
    const int tid  = threadIdx.x;
    const int wid  = tid >> 5;
    const int lane = tid & 31;
    const int m0 = (wid >> 2) * 32;
    const int n0 = (wid & 3) * 32;

    const int lrow = tid >> 2;
    const int lkc  = tid & 3;
    const int ldst = toff(lrow, lkc * 8);
    const size_t lasrc = (size_t)(bm + lrow) * DIMC + lkc * 8;
    const size_t lwsrc = (size_t)(bn + lrow) * DIMC + lkc * 8;

    char* bufs[NSTG] = { dynsmem, dynsmem + STG, dynsmem + 2*STG };

    auto issue = [&](int k0, char* bp) {
        cpa16(bp          + ldst, Ah + lasrc + k0);
        cpa16(bp + 8192   + ldst, Al + lasrc + k0);
        cpa16(bp + 16384  + ldst, Wh + lwsrc + k0);
        cpa16(bp + 24576  + ldst, Wl + lwsrc + k0);
    };

    float acc[2][4][4];
    #pragma unroll
    for (int a = 0; a < 2; a++)
        #pragma unroll
        for (int b = 0; b < 4; b++)
            #pragma unroll
            for (int c = 0; c < 4; c++) acc[a][b][c] = 0.f;

    const int ar  = lane & 15;
    const int akh = (lane >> 4) * 8;
    const int br  = (lane & 7) + ((lane >> 4) << 3);
    const int bkh = ((lane >> 3) & 1) * 8;

    issue(0, bufs[0]);       CP_COMMIT();
    issue(TBK, bufs[1]);     CP_COMMIT();

    const int NSLAB = DIMC / TBK;       // 32
    for (int i = 0; i < NSLAB; i++) {
        cp_wait<1>();
        __syncthreads();
        // refill the buffer freed by slab i-1 (done before this barrier)
        if (i + 2 < NSLAB) issue((i + 2) * TBK, bufs[(i + 2) % NSTG]);
        CP_COMMIT();        // uniform group count (empty near the tail)

        char* bp = bufs[i % NSTG];
        #pragma unroll
        for (int kk = 0; kk < 2; kk++) {
            const int kb = kk * 16;
            uint32_t Ahf[2][4], Alf[2][4], Bhf[2][4], Blf[2][4];
            #pragma unroll
            for (int mt = 0; mt < 2; mt++) {
                int o = toff(m0 + mt*16 + ar, kb + akh) + ((kb + akh) & 7) * 2;
                ldmx4(Ahf[mt], bp + o);
                ldmx4(Alf[mt], bp + 8192 + o);
            }
            #pragma unroll
            for (int np = 0; np < 2; np++) {
                int o = toff(n0 + np*16 + br, kb + bkh) + ((kb + bkh) & 7) * 2;
                ldmx4(Bhf[np], bp + 16384 + o);
                ldmx4(Blf[np], bp + 24576 + o);
            }
            #pragma unroll
            for (int mt = 0; mt < 2; mt++)
                #pragma unroll
                for (int nt = 0; nt < 4; nt++) {
                    const int np = nt >> 1, pr = (nt & 1) * 2;
                    mma16816(acc[mt][nt], Ahf[mt], Bhf[np][pr], Bhf[np][pr+1]);
                    mma16816(acc[mt][nt], Alf[mt], Bhf[np][pr], Bhf[np][pr+1]);
                    mma16816(acc[mt][nt], Ahf[mt], Blf[np][pr], Blf[np][pr+1]);
                }
        }
    }

    __half* Chalf = (osel == 0) ? g_qh : (osel == 1) ? g_kh : g_vh;
    #pragma unroll
    for (int mt = 0; mt < 2; mt++) {
        const int r = bm + m0 + mt*16 + (lane >> 2);
        #pragma unroll
        for (int nt = 0; nt < 4; nt++) {
            const int c = bn + n0 + nt*8 + (lane & 3) * 2;
            const float b0 = bias[c], b1 = bias[c + 1];
            if (osel < 3) {
                *(__half2*)(Chalf + (size_t)r * DIMC + c) =
                    __floats2half2_rn((acc[mt][nt][0] + b0) * oscale,
                                      (acc[mt][nt][1] + b1) * oscale);
                *(__half2*)(Chalf + (size_t)(r + 8) * DIMC + c) =
                    __floats2half2_rn((acc[mt][nt][2] + b0) * oscale,
                                      (acc[mt][nt][3] + b1) * oscale);
            } else {
                *(float2*)(Cext + (size_t)r * DIMC + c) =
                    make_float2(acc[mt][nt][0] + b0, acc[mt][nt][1] + b1);
                *(float2*)(Cext + (size_t)(r + 8) * DIMC + c) =
                    make_float2(acc[mt][nt][2] + b0, acc[mt][nt][3] + b1);
            }
        }
    }
}

// ============================================================================
// Flash attention: fp16 gmem I/O, 3-stage cp.async K/V ring, ONE sync/tile.
// Dynamic smem 64KB: Q 16K + 3 x (K 8K | V 8K). 2 CTAs/SM.
// ============================================================================
__global__ __launch_bounds__(256, 2)
void attn_tc()
{
    char* sQ = dynsmem;                       // 16384 B

    const int b  = blockIdx.z;
    const int h  = blockIdx.y;
    const int q0 = blockIdx.x * 128;
    const int tid  = threadIdx.x;
    const int wid  = tid >> 5;
    const int lane = tid & 31;

    const __half* Qg = g_qh + (size_t)(b*SEQL + q0)*DIMC + h*HDIM;
    const __half* Kg = g_kh + (size_t)(b*SEQL)*DIMC + h*HDIM;
    const __half* Vg = g_vh + (size_t)(b*SEQL)*DIMC + h*HDIM;

    auto kbuf = [&](int p) { return dynsmem + 16384 + p * 16384; };
    auto vbuf = [&](int p) { return dynsmem + 16384 + p * 16384 + 8192; };

    auto issueKV = [&](int t0, int p) {
        char* kb = kbuf(p); char* vb = vbuf(p);
        #pragma unroll
        for (int l = 0; l < 2; l++) {
            int u = tid + l*256;
            int row = u >> 3, seg = u & 7;
            int so = row*128 + ((seg ^ (row & 7)) * 16);
            cpa16(kb + so, Kg + (size_t)(t0+row)*DIMC + seg*8);
            cpa16(vb + so, Vg + (size_t)(t0+row)*DIMC + seg*8);
        }
    };

    // prologue: Q rides with KV tile 0 in group 0; tile 1 in group 1
    #pragma unroll
    for (int l = 0; l < 4; l++) {
        int u = tid + l*256;
        int row = u >> 3, seg = u & 7;
        cpa16(sQ + row*128 + ((seg ^ (row & 7)) * 16),
              Qg + (size_t)row*DIMC + seg*8);
    }
    issueKV(0, 0);   CP_COMMIT();
    issueKV(64, 1);  CP_COMMIT();

    const int krow_off = (lane & 7) + ((lane >> 4) * 8);
    const int kd_sub   = (lane >> 3) & 1;
    const int vrow_off = lane & 15;
    const int vd_sub   = lane >> 4;

    uint32_t qf[4][4];
    float m0 = -1e30f, m1 = -1e30f, l0 = 0.f, l1 = 0.f;
    float oacc[8][4];
    #pragma unroll
    for (int t = 0; t < 8; t++) { oacc[t][0]=0.f; oacc[t][1]=0.f; oacc[t][2]=0.f; oacc[t][3]=0.f; }

    const int NT = SEQL / 64;   // 32
    for (int t = 0; t < NT; t++) {
        cp_wait<1>();
        __syncthreads();
        if (t == 0) {   // hoist Q fragments once (Q arrived with group 0)
            int r = wid*16 + (lane & 15);
            char* rb = sQ + r*128;
            int rx = r & 7;
            #pragma unroll
            for (int ks = 0; ks < 4; ks++) {
                int c = ks*2 + (lane >> 4);
                ldmx4(qf[ks], rb + ((c ^ rx) * 16));
            }
        }
        if (t + 2 < NT) issueKV((t + 2) * 64, (t + 2) % 3);
        CP_COMMIT();

        char* sK = kbuf(t % 3);
        char* sV = vbuf(t % 3);

        // ---- S = Q K^T ----
        float sacc[8][4];
        #pragma unroll
        for (int u = 0; u < 8; u++) { sacc[u][0]=0.f; sacc[u][1]=0.f; sacc[u][2]=0.f; sacc[u][3]=0.f; }
        #pragma unroll
        for (int ks = 0; ks < 4; ks++) {
            uint32_t kf[4][4];
            #pragma unroll
            for (int nb = 0; nb < 4; nb++) {
                int key = nb*16 + krow_off;
                int c = ks*2 + kd_sub;
                ldmx4(kf[nb], sK + key*128 + ((c ^ (key & 7)) * 16));
            }
            #pragma unroll
            for (int nb = 0; nb < 4; nb++) {
                mmaf16(sacc[2*nb],   qf[ks], kf[nb][0], kf[nb][1]);
                mmaf16(sacc[2*nb+1], qf[ks], kf[nb][2], kf[nb][3]);
            }
        }

        // ---- online softmax ----
        float mx0 = -1e30f, mx1 = -1e30f;
        #pragma unroll
        for (int u = 0; u < 8; u++) {
            mx0 = fmaxf(mx0, fmaxf(sacc[u][0], sacc[u][1]));
            mx1 = fmaxf(mx1, fmaxf(sacc[u][2], sacc[u][3]));
        }
        mx0 = fmaxf(mx0, __shfl_xor_sync(0xffffffffu, mx0, 1));
        mx0 = fmaxf(mx0, __shfl_xor_sync(0xffffffffu, mx0, 2));
        mx1 = fmaxf(mx1, __shfl_xor_sync(0xffffffffu, mx1, 1));
        mx1 = fmaxf(mx1, __shfl_xor_sync(0xffffffffu, mx1, 2));
        float mn0 = fmaxf(m0, mx0), mn1 = fmaxf(m1, mx1);
        float al0 = __expf(m0 - mn0), al1 = __expf(m1 - mn1);
        float ls0 = 0.f, ls1 = 0.f;
        #pragma unroll
        for (int u = 0; u < 8; u++) {
            sacc[u][0] = __expf(sacc[u][0] - mn0);
            sacc[u][1] = __expf(sacc[u][1] - mn0);
            sacc[u][2] = __expf(sacc[u][2] - mn1);
            sacc[u][3] = __expf(sacc[u][3] - mn1);
            ls0 += sacc[u][0] + sacc[u][1];
            ls1 += sacc[u][2] + sacc[u][3];
        }
        ls0 += __shfl_xor_sync(0xffffffffu, ls0, 1);
        ls0 += __shfl_xor_sync(0xffffffffu, ls0, 2);
        ls1 += __shfl_xor_sync(0xffffffffu, ls1, 1);
        ls1 += __shfl_xor_sync(0xffffffffu, ls1, 2);
        l0 = l0*al0 + ls0;  m0 = mn0;
        l1 = l1*al1 + ls1;  m1 = mn1;
        #pragma unroll
        for (int u = 0; u < 8; u++) {
            oacc[u][0] *= al0; oacc[u][1] *= al0;
            oacc[u][2] *= al1; oacc[u][3] *= al1;
        }

        // ---- O += P V (register identity) ----
        #pragma unroll
        for (int j = 0; j < 4; j++) {
            uint32_t a[4];
            a[0] = pack_h2(sacc[2*j][0],   sacc[2*j][1]);
            a[1] = pack_h2(sacc[2*j][2],   sacc[2*j][3]);
            a[2] = pack_h2(sacc[2*j+1][0], sacc[2*j+1][1]);
            a[3] = pack_h2(sacc[2*j+1][2], sacc[2*j+1][3]);
            uint32_t vf[4][4];
            #pragma unroll
            for (int nb = 0; nb < 4; nb++) {
                int row = j*16 + vrow_off;
                int c = nb*2 + vd_sub;
                ldmx4t(vf[nb], sV + row*128 + ((c ^ (row & 7)) * 16));
            }
            #pragma unroll
            for (int nb = 0; nb < 4; nb++) {
                mmaf16(oacc[2*nb],   a, vf[nb][0], vf[nb][1]);
                mmaf16(oacc[2*nb+1], a, vf[nb][2], vf[nb][3]);
            }
        }
    }

    // ---- normalize + bf16 hi/lo split epilogue ----
    const float inv0 = 1.0f / l0, inv1 = 1.0f / l1;
    const int r = q0 + wid*16 + (lane >> 2);
    const size_t base0 = (size_t)(b*SEQL + r) * DIMC + h*HDIM + (lane & 3)*2;
    const size_t base1 = base0 + (size_t)8 * DIMC;
    #pragma unroll
    for (int t = 0; t < 8; t++) {
        float o0 = oacc[t][0]*inv0, o1 = oacc[t][1]*inv0;
        float o2 = oacc[t][2]*inv1, o3 = oacc[t][3]*inv1;
        __nv_bfloat16 h0 = __float2bfloat16(o0), h1 = __float2bfloat16(o1);
        __nv_bfloat16 h2 = __float2bfloat16(o2), h3 = __float2bfloat16(o3);
        __nv_bfloat162 hv, lv;
        hv.x = h0; hv.y = h1;
        lv.x = __float2bfloat16(o0 - __bfloat162float(h0));
        lv.y = __float2bfloat16(o1 - __bfloat162float(h1));
        *(__nv_bfloat162*)(g_aoh + base0 + t*8) = hv;
        *(__nv_bfloat162*)(g_aol + base0 + t*8) = lv;
        hv.x = h2; hv.y = h3;
        lv.x = __float2bfloat16(o2 - __bfloat162float(h2));
        lv.y = __float2bfloat16(o3 - __bfloat162float(h3));
        *(__nv_bfloat162*)(g_aoh + base1 + t*8) = hv;
        *(__nv_bfloat162*)(g_aol + base1 + t*8) = lv;
    }
}

extern "C" void kernel_launch(void* const* d_in, const int* in_sizes, int n_in,
                              void* d_out, int out_size)
{
    const float* x   = (const float*)d_in[0];
    const float* ctx = (const float*)d_in[1];
    const float* Wq  = (const float*)d_in[2];
    const float* bq  = (const float*)d_in[3];
    const float* Wk  = (const float*)d_in[4];
    const float* bk  = (const float*)d_in[5];
    const float* Wv  = (const float*)d_in[6];
    const float* bv  = (const float*)d_in[7];
    const float* Wo  = (const float*)d_in[8];
    const float* bo  = (const float*)d_in[9];
    float* out = (float*)d_out;

    cudaFuncSetAttribute(gemm_tc3,
        cudaFuncAttributeMaxDynamicSharedMemorySize, NSTG * STG);
    cudaFuncSetAttribute(attn_tc,
        cudaFuncAttributeMaxDynamicSharedMemorySize, 65536);

    // splits: activations 2 x (8192x1024), weights 4 x (1024x1024)
    split_act_k<<<dim3(2048, 2), 256>>>(x, ctx);
    split_w_k<<<dim3(256, 4), 256>>>(Wq, Wk, Wv, Wo);

    dim3 gg(DIMC / TBN, NROWS / TBM);   // (8, 64)
    gemm_tc3<<<gg, 512, NSTG*STG>>>(bq, nullptr, 0, 0, 0, 0.125f);  // Q
    gemm_tc3<<<gg, 512, NSTG*STG>>>(bk, nullptr, 1, 1, 1, 1.0f);    // K
    gemm_tc3<<<gg, 512, NSTG*STG>>>(bv, nullptr, 1, 2, 2, 1.0f);    // V
    attn_tc<<<dim3(SEQL/128, NHEADS, BATCH), 256, 65536>>>();       // attention
    gemm_tc3<<<gg, 512, NSTG*STG>>>(bo, out, 2, 3, 3, 1.0f);        // O proj
}